// round 6
// baseline (speedup 1.0000x reference)
#include <cuda_runtime.h>

#define B_    16384
#define T_    64
#define NB    8          // batch elems per CTA
#define NTHR  256        // 16 groups (8 elems x 2 dirs) x 16 lanes
#define EPAD  2050       // floats per elem tile: 64*32 + 2 pad (bank skew)

typedef unsigned long long u64;

struct Smem {
    u64   wi[2][48][17];          // [dir][gate_row][k-pair], padded stride 17
    u64   wh[2][48][9];           // [dir][gate_row][k-pair], padded stride 9
    float actA[NB][EPAD];
    float actB[NB][EPAD];
    float bR[2][16], bZ[2][16], bNX[2][16], bNH[2][16];
    float wcw[4][32];
    float wcb[4];
};

__device__ __forceinline__ u64 pack2(float lo, float hi) {
    u64 r; asm("mov.b64 %0, {%1, %2};" : "=l"(r) : "f"(lo), "f"(hi)); return r;
}
__device__ __forceinline__ void unpack2(u64 d, float& lo, float& hi) {
    asm("mov.b64 {%0, %1}, %2;" : "=f"(lo), "=f"(hi) : "l"(d));
}
__device__ __forceinline__ u64 ffma2(u64 a, u64 b, u64 c) {
    u64 d; asm("fma.rn.f32x2 %0, %1, %2, %3;" : "=l"(d) : "l"(a), "l"(b), "l"(c)); return d;
}
__device__ __forceinline__ float hadd(u64 v) {
    float lo, hi; unpack2(v, lo, hi); return lo + hi;
}
__device__ __forceinline__ float sigm(float x) {
    return __fdividef(1.f, 1.f + __expf(-x));
}
__device__ __forceinline__ float tanhfast(float x) {
    float a = fabsf(x);
    float e = __expf(-2.f * a);
    float t = __fdividef(1.f - e, 1.f + e);
    return copysignf(t, x);
}

// Stage one layer's weights into smem as f32x2 pairs (coalesced global reads).
__device__ __forceinline__ void stage_layer(Smem* s,
        const float* __restrict__ Wi, const float* __restrict__ Wh,
        const float* __restrict__ bi, const float* __restrict__ bh,
        int F, int KP, int tid)
{
    for (int i = tid; i < 2 * 48 * KP; i += NTHR) {
        int d = i / (48 * KP); int r = i - d * 48 * KP;
        int row = r / KP, kp = r - row * KP;
        const float* w = Wi + ((size_t)d * 48 + row) * F;
        float lo = w[2 * kp];
        float hi = (2 * kp + 1 < F) ? w[2 * kp + 1] : 0.f;
        s->wi[d][row][kp] = pack2(lo, hi);
    }
    for (int i = tid; i < 2 * 48 * 8; i += NTHR) {
        int d = i / (48 * 8); int r = i - d * 48 * 8;
        int row = r >> 3, kp = r & 7;
        const float* w = Wh + ((size_t)d * 48 + row) * 16;
        s->wh[d][row][kp] = pack2(w[2 * kp], w[2 * kp + 1]);
    }
    for (int i = tid; i < 2 * 16; i += NTHR) {
        int d = i >> 4, uu = i & 15;
        s->bR[d][uu]  = bi[d * 48 + uu]      + bh[d * 48 + uu];
        s->bZ[d][uu]  = bi[d * 48 + 16 + uu] + bh[d * 48 + 16 + uu];
        s->bNX[d][uu] = bi[d * 48 + 32 + uu];
        s->bNH[d][uu] = bh[d * 48 + 32 + uu];
    }
}

// One bidirectional GRU layer. Lane u of group (elem,dir) owns hidden unit u.
// Recurrent h-vector is re-read from the y-tile written last step (syncwarp-
// ordered; groups are 16-lane aligned and warps are same-direction).
template <int KP>
__device__ __forceinline__ void run_layer(Smem* s,
        const float (*rd)[EPAD], float (*wr)[EPAD],
        int elem, int dir, int u)
{
    u64 wir[KP], wiz[KP], win[KP];
#pragma unroll
    for (int k = 0; k < KP; k++) {
        wir[k] = s->wi[dir][u][k];
        wiz[k] = s->wi[dir][16 + u][k];
        win[k] = s->wi[dir][32 + u][k];
    }
    u64 whr[8], whz[8], whn[8];
#pragma unroll
    for (int k = 0; k < 8; k++) {
        whr[k] = s->wh[dir][u][k];
        whz[k] = s->wh[dir][16 + u][k];
        whn[k] = s->wh[dir][32 + u][k];
    }
    const float br  = s->bR[dir][u],  bz  = s->bZ[dir][u];
    const float bnx = s->bNX[dir][u], bnh = s->bNH[dir][u];

    float h = 0.f;
    const int wcol = dir * 16 + u;
    int prev_t = 0;

    for (int ti = 0; ti < T_; ++ti) {
        const int t = dir ? (T_ - 1 - ti) : ti;

        const u64* xp = (const u64*)&rd[elem][t * 32];
        u64 ar = 0, az = 0, anx = 0;
#pragma unroll
        for (int k = 0; k < KP; k++) {
            u64 xv = xp[k];
            ar  = ffma2(wir[k], xv, ar);
            az  = ffma2(wiz[k], xv, az);
            anx = ffma2(win[k], xv, anx);
        }

        u64 arh = 0, azh = 0, anh = 0;
        if (ti > 0) {
            const u64* hp = (const u64*)&wr[elem][prev_t * 32 + dir * 16];
#pragma unroll
            for (int k = 0; k < 8; k++) {
                u64 hv = hp[k];
                arh = ffma2(whr[k], hv, arh);
                azh = ffma2(whz[k], hv, azh);
                anh = ffma2(whn[k], hv, anh);
            }
        }

        float r = sigm(hadd(ar) + hadd(arh) + br);
        float z = sigm(hadd(az) + hadd(azh) + bz);
        float n = tanhfast(fmaf(r, hadd(anh) + bnh, hadd(anx) + bnx));
        h = fmaf(z, h - n, n);              // (1-z)*n + z*h

        wr[elem][t * 32 + wcol] = h;
        prev_t = t;
        __syncwarp();                        // h-tile visible to group next step
    }
}

extern "C" __global__ void __launch_bounds__(NTHR)
fused_gru(const float* __restrict__ x,
          const float* __restrict__ Wi1, const float* __restrict__ Wh1,
          const float* __restrict__ bi1, const float* __restrict__ bh1,
          const float* __restrict__ Wi5, const float* __restrict__ Wh5,
          const float* __restrict__ bi5, const float* __restrict__ bh5,
          const float* __restrict__ Wc,  const float* __restrict__ bc,
          float* __restrict__ out)
{
    extern __shared__ __align__(16) unsigned char smraw[];
    Smem* s = reinterpret_cast<Smem*>(smraw);

    const int tid  = threadIdx.x;
    const int u    = tid & 15;
    const int g    = tid >> 4;        // warp w holds groups 2w,2w+1 (same dir)
    const int dir  = g >> 3;
    const int elem = g & 7;

    // Stage layer-0 input x[B,T,3] into actA channels 0..3 (ch3 zeroed).
    for (int i = tid; i < NB * T_ * 4; i += NTHR) {
        int e = i >> 8; int r = i & 255; int t = r >> 2; int c = r & 3;
        float v = 0.f;
        if (c < 3) v = x[((size_t)blockIdx.x * NB + e) * (T_ * 3) + t * 3 + c];
        s->actA[e][t * 32 + c] = v;
    }
    // Stage classifier weights once.
    for (int i = tid; i < 128; i += NTHR) s->wcw[i >> 5][i & 31] = Wc[i];
    if (tid < 4) s->wcb[tid] = bc[tid];

    // Layer 0 (F=3, padded to 4 -> KP=2): actA -> actB
    stage_layer(s, Wi1, Wh1, bi1, bh1, 3, 2, tid);
    __syncthreads();
    run_layer<2>(s, s->actA, s->actB, elem, dir, u);
    __syncthreads();

    // Layers 1..5 (F=32, KP=16), ping-pong. Final output lands in actA.
#pragma unroll 1
    for (int l = 0; l < 5; l++) {
        stage_layer(s, Wi5 + (size_t)l * 3072, Wh5 + (size_t)l * 1536,
                    bi5 + (size_t)l * 96, bh5 + (size_t)l * 96, 32, 16, tid);
        __syncthreads();
        if (l & 1) run_layer<16>(s, s->actA, s->actB, elem, dir, u);
        else       run_layer<16>(s, s->actB, s->actA, elem, dir, u);
        __syncthreads();
    }

    // Classifier + softmax, straight from smem to d_out (coalesced float4).
    for (int i = tid; i < NB * T_; i += NTHR) {
        int e = i >> 6, t = i & 63;
        const u64* yp = (const u64*)&s->actA[e][t * 32];
        const u64* w0 = (const u64*)&s->wcw[0][0];
        const u64* w1 = (const u64*)&s->wcw[1][0];
        const u64* w2 = (const u64*)&s->wcw[2][0];
        const u64* w3 = (const u64*)&s->wcw[3][0];
        u64 a0 = 0, a1 = 0, a2 = 0, a3 = 0;
#pragma unroll
        for (int k = 0; k < 16; k++) {
            u64 yv = yp[k];
            a0 = ffma2(w0[k], yv, a0);
            a1 = ffma2(w1[k], yv, a1);
            a2 = ffma2(w2[k], yv, a2);
            a3 = ffma2(w3[k], yv, a3);
        }
        float l0 = hadd(a0) + s->wcb[0];
        float l1 = hadd(a1) + s->wcb[1];
        float l2 = hadd(a2) + s->wcb[2];
        float l3 = hadd(a3) + s->wcb[3];
        float m  = fmaxf(fmaxf(l0, l1), fmaxf(l2, l3));
        float e0 = __expf(l0 - m), e1 = __expf(l1 - m);
        float e2 = __expf(l2 - m), e3 = __expf(l3 - m);
        float rs = __fdividef(1.f, e0 + e1 + e2 + e3);
        float4 o = make_float4(e0 * rs, e1 * rs, e2 * rs, e3 * rs);
        reinterpret_cast<float4*>(out)[((size_t)blockIdx.x * NB + e) * T_ + t] = o;
    }
}

extern "C" void kernel_launch(void* const* d_in, const int* in_sizes, int n_in,
                              void* d_out, int out_size)
{
    const float* x   = (const float*)d_in[0];
    const float* Wi1 = (const float*)d_in[1];
    const float* Wh1 = (const float*)d_in[2];
    const float* bi1 = (const float*)d_in[3];
    const float* bh1 = (const float*)d_in[4];
    const float* Wi5 = (const float*)d_in[5];
    const float* Wh5 = (const float*)d_in[6];
    const float* bi5 = (const float*)d_in[7];
    const float* bh5 = (const float*)d_in[8];
    const float* Wc  = (const float*)d_in[9];
    const float* bc  = (const float*)d_in[10];
    float* out = (float*)d_out;

    static bool once = []() {
        cudaFuncSetAttribute(fused_gru,
            cudaFuncAttributeMaxDynamicSharedMemorySize, (int)sizeof(Smem));
        return true;
    }();
    (void)once;

    fused_gru<<<B_ / NB, NTHR, sizeof(Smem)>>>(
        x, Wi1, Wh1, bi1, bh1, Wi5, Wh5, bi5, bh5, Wc, bc, out);
}